// round 13
// baseline (speedup 1.0000x reference)
#include <cuda_runtime.h>
#include <cuda.h>
#include <cuda_fp16.h>
#include <cstdint>

// ---------------------------------------------------------------------------
// Geometry
// ---------------------------------------------------------------------------
#define D        2048
#define M_X      8193
#define M_TOT    8225              // x rows + 32 x_true rows
#define M_PAD    8320              // 65 * 128
#define ROW_ADDW 8193
#define ROW_ADDB 12289
#define ROW_NOISE 14337
#define XOUT_ROWS 14338
#define NW 4096
#define NB 2048

#define XMIN_OFF  ((size_t)XOUT_ROWS * D)
#define XMAX_OFF  (XMIN_OFF + D)
#define XTRUE_OFF (XMAX_OFF + D)

// partial slots: 65 gemm CTA-rows + 1 scatter-atomic slot + 1 noise slot = 67
#define GP_GEMM   0
#define GP_SCAT   65
#define GP_NOISE  66
#define GP_TOTAL  67
__device__ float g_partial[128 * D];

// fp16 buffers (scratch via __device__ globals — allowed)
__device__ __align__(1024) __half g_Ah[(size_t)M_PAD * D];
__device__ __align__(1024) __half g_Bh[(size_t)D * D];

// ---------------------------------------------------------------------------
// PTX helpers (baseline sm_90 features only — NO tcgen05 on this toolchain)
// ---------------------------------------------------------------------------
__device__ __forceinline__ uint32_t s2u(const void* p) {
    return (uint32_t)__cvta_generic_to_shared(p);
}

#define MBAR_INIT(a, n) \
    asm volatile("mbarrier.init.shared.b64 [%0], %1;" :: "r"(a), "r"((uint32_t)(n)) : "memory")
#define MBAR_EXPECT_TX(a, b) \
    asm volatile("mbarrier.arrive.expect_tx.shared.b64 _, [%0], %1;" :: "r"(a), "r"((uint32_t)(b)) : "memory")
#define MBAR_ARRIVE(a) \
    asm volatile("mbarrier.arrive.shared.b64 _, [%0];" :: "r"(a) : "memory")

__device__ __forceinline__ void mbar_wait(uint32_t mbar, uint32_t parity) {
    asm volatile(
        "{\n\t.reg .pred P;\n\t"
        "WL_%=:\n\t"
        "mbarrier.try_wait.parity.acquire.cta.shared::cta.b64 P, [%0], %1, 0x989680;\n\t"
        "@P bra.uni WD_%=;\n\t"
        "bra.uni WL_%=;\n\t"
        "WD_%=:\n\t}"
        :: "r"(mbar), "r"(parity) : "memory");
}

#define TMA_LD2D(saddr, map, cx, cy, mbar) \
    asm volatile("cp.async.bulk.tensor.2d.shared::cta.global.tile.mbarrier::complete_tx::bytes " \
                 "[%0], [%1, {%2, %3}], [%4];" \
                 :: "r"(saddr), "l"(map), "r"(cx), "r"(cy), "r"(mbar) : "memory")

#define LDSM_X4(d0, d1, d2, d3, a) \
    asm volatile("ldmatrix.sync.aligned.m8n8.x4.shared.b16 {%0,%1,%2,%3}, [%4];" \
                 : "=r"(d0), "=r"(d1), "=r"(d2), "=r"(d3) : "r"(a))

#define MMA_F16(c0, c1, c2, c3, a0, a1, a2, a3, b0, b1) \
    asm volatile("mma.sync.aligned.m16n8k16.row.col.f32.f16.f16.f32 " \
                 "{%0,%1,%2,%3}, {%4,%5,%6,%7}, {%8,%9}, {%0,%1,%2,%3};" \
                 : "+f"(c0), "+f"(c1), "+f"(c2), "+f"(c3) \
                 : "r"(a0), "r"(a1), "r"(a2), "r"(a3), "r"(b0), "r"(b1))

// ---------------------------------------------------------------------------
// GEMM config: 128x128 CTA tile, KC=64 per stage, 3-stage TMA pipeline,
// 2 CTAs/SM (96 KB smem, <=128 regs). 8 warps, 64x32 warp tiles.
// empty_mb uses per-warp elected arrives (count 8) — 1/32 the shared-pipe
// atomic traffic vs all-thread arrives.
// ---------------------------------------------------------------------------
#define MT 128
#define NT 128
#define KC 64
#define NSTAGE 3
#define NKIT (D / KC)               // 32
#define TILE_B   (128 * 128)        // 16384 B
#define STAGE_B  (2 * TILE_B)       // A, B = 32768 B
#define SM_TOTAL (NSTAGE * STAGE_B) // 98304 B

__global__ __launch_bounds__(256, 2) void gemm_hmma(
    const __grid_constant__ CUtensorMap tA,
    const __grid_constant__ CUtensorMap tB,
    const float* __restrict__ bias,
    float* __restrict__ out)
{
    extern __shared__ __align__(1024) char smem[];
    __shared__ __align__(8) uint64_t full_mb[NSTAGE];
    __shared__ __align__(8) uint64_t empty_mb[NSTAGE];

    const uint32_t sb  = s2u(smem);
    const int tid = threadIdx.x;
    const int wid = tid >> 5, lane = tid & 31;
    const int m0 = blockIdx.y * MT, n0 = blockIdx.x * NT;
    const int wy = wid & 1, wx = wid >> 1;          // warp tile 64(M) x 32(N)
    const int wm = wy * 64, wn = wx * 32;

    if (tid == 0) {
        #pragma unroll
        for (int s = 0; s < NSTAGE; ++s) {
            MBAR_INIT(s2u(&full_mb[s]), 1);
            MBAR_INIT(s2u(&empty_mb[s]), 8);   // one elected arrive per warp
        }
    }
    asm volatile("fence.proxy.async.shared::cta;" ::: "memory");
    __syncthreads();

    // prologue: fill all stages
    if (tid == 0) {
        #pragma unroll
        for (int s = 0; s < NSTAGE; ++s) {
            uint32_t mb = s2u(&full_mb[s]);
            MBAR_EXPECT_TX(mb, STAGE_B);
            uint32_t sp = sb + s * STAGE_B;
            int k0 = s * KC;
            TMA_LD2D(sp,          &tA, k0, m0, mb);
            TMA_LD2D(sp + TILE_B, &tB, k0, n0, mb);
        }
    }

    // per-lane ldmatrix address pieces (SW128: chunk' = chunk ^ (row & 7))
    const int rA  = wm + ((lane >> 3) & 1) * 8 + (lane & 7);
    const int cgA = (lane >> 4) & 1;
    const int rB  = wn + ((lane >> 4) & 1) * 8 + (lane & 7);
    const int cgB = (lane >> 3) & 1;
    const int swA = rA & 7, swB = rB & 7;

    float acc[4][4][4];
    #pragma unroll
    for (int i = 0; i < 4; i++)
        #pragma unroll
        for (int j = 0; j < 4; j++)
            #pragma unroll
            for (int k = 0; k < 4; k++) acc[i][j][k] = 0.f;

    uint32_t A0[4][4], B0[4][2], A1[4][4], B1[4][2];

    #define LOAD_FRAGS(Af, Bf, sA, sB, ks)                                    \
        do {                                                                  \
            _Pragma("unroll")                                                 \
            for (int mi = 0; mi < 4; ++mi) {                                  \
                uint32_t a = (sA) + (rA + mi * 16) * 128                      \
                           + (((2 * (ks) + cgA) ^ swA) << 4);                 \
                LDSM_X4(Af[mi][0], Af[mi][1], Af[mi][2], Af[mi][3], a);       \
            }                                                                 \
            _Pragma("unroll")                                                 \
            for (int nb = 0; nb < 2; ++nb) {                                  \
                uint32_t a = (sB) + (rB + nb * 16) * 128                      \
                           + (((2 * (ks) + cgB) ^ swB) << 4);                 \
                LDSM_X4(Bf[nb * 2][0], Bf[nb * 2][1],                         \
                        Bf[nb * 2 + 1][0], Bf[nb * 2 + 1][1], a);             \
            }                                                                 \
        } while (0)

    #define MMA_ALL(Af, Bf)                                                   \
        do {                                                                  \
            _Pragma("unroll")                                                 \
            for (int mi = 0; mi < 4; ++mi)                                    \
                _Pragma("unroll")                                             \
                for (int nj = 0; nj < 4; ++nj)                                \
                    MMA_F16(acc[mi][nj][0], acc[mi][nj][1],                   \
                            acc[mi][nj][2], acc[mi][nj][3],                   \
                            Af[mi][0], Af[mi][1], Af[mi][2], Af[mi][3],       \
                            Bf[nj][0], Bf[nj][1]);                            \
        } while (0)

    for (int it = 0; it < NKIT; ++it) {
        const int slot = it % NSTAGE;
        const uint32_t ph = (uint32_t)((it / NSTAGE) & 1);
        mbar_wait(s2u(&full_mb[slot]), ph);

        const uint32_t sA = sb + slot * STAGE_B;
        const uint32_t sB = sA + TILE_B;

        LOAD_FRAGS(A0, B0, sA, sB, 0);
        LOAD_FRAGS(A1, B1, sA, sB, 1);
        MMA_ALL(A0, B0);
        LOAD_FRAGS(A0, B0, sA, sB, 2);
        MMA_ALL(A1, B1);
        LOAD_FRAGS(A1, B1, sA, sB, 3);
        // all LDSM reads of this slot done (ldmatrix is warp-synchronous):
        // one elected arrive per warp
        if (lane == 0) MBAR_ARRIVE(s2u(&empty_mb[slot]));
        MMA_ALL(A0, B0);
        MMA_ALL(A1, B1);

        // producer refill (only tid 0): wait all 8 warps released slot
        const int nx = it + NSTAGE;
        if (tid == 0 && nx < NKIT) {
            mbar_wait(s2u(&empty_mb[slot]), (uint32_t)((it / NSTAGE) & 1));
            uint32_t mb = s2u(&full_mb[slot]);
            MBAR_EXPECT_TX(mb, STAGE_B);
            uint32_t spn = sb + slot * STAGE_B;
            int k0 = nx * KC;
            TMA_LD2D(spn,          &tA, k0, m0, mb);
            TMA_LD2D(spn + TILE_B, &tB, k0, n0, mb);
        }
    }

    #undef LOAD_FRAGS
    #undef MMA_ALL

    // ---- epilogue: stores + fused |.| column partial over eps rows ----
    float colsum[4][2];
    #pragma unroll
    for (int nj = 0; nj < 4; ++nj) { colsum[nj][0] = 0.f; colsum[nj][1] = 0.f; }

    #pragma unroll
    for (int mi = 0; mi < 4; ++mi) {
        #pragma unroll
        for (int half = 0; half < 2; ++half) {
            int gm = m0 + wm + mi * 16 + (lane >> 2) + half * 8;
            if (gm >= M_TOT) continue;
            bool addb = (gm == 0) || (gm >= M_X);
            bool inabs = (gm >= 1) && (gm < M_X);     // eps rows only
            size_t base = (gm < M_X) ? (size_t)gm * D
                                     : XTRUE_OFF + (size_t)(gm - M_X) * D;
            #pragma unroll
            for (int nj = 0; nj < 4; ++nj) {
                int col = n0 + wn + nj * 8 + 2 * (lane & 3);
                float2 v;
                v.x = acc[mi][nj][half * 2 + 0];
                v.y = acc[mi][nj][half * 2 + 1];
                if (inabs) {
                    colsum[nj][0] += fabsf(v.x);
                    colsum[nj][1] += fabsf(v.y);
                }
                if (addb) { v.x += bias[col]; v.y += bias[col + 1]; }
                *reinterpret_cast<float2*>(&out[base + col]) = v;
            }
        }
    }

    // deterministic CTA-level column reduction: 16 contributors per column
    float* red = reinterpret_cast<float*>(smem);      // 128 cols x 16 = 8 KB
    const int cid = wy * 8 + (lane >> 2);
    __syncthreads();                                   // smem reuse safe
    #pragma unroll
    for (int nj = 0; nj < 4; ++nj) {
        int c0 = wn + nj * 8 + 2 * (lane & 3);
        red[(c0 + 0) * 16 + cid] = colsum[nj][0];
        red[(c0 + 1) * 16 + cid] = colsum[nj][1];
    }
    __syncthreads();
    if (tid < 128) {
        float s = 0.f;
        #pragma unroll
        for (int c = 0; c < 16; ++c) s += red[tid * 16 + c];
        g_partial[(size_t)(GP_GEMM + blockIdx.y) * D + n0 + tid] = s;
    }
}

// ---------------------------------------------------------------------------
// fp16 conversion — 8 elements per thread (2x float4 in, 1x uint4 out)
// ---------------------------------------------------------------------------
__device__ __forceinline__ uint2 cvt4(float4 v) {
    __half2 h0 = __floats2half2_rn(v.x, v.y);
    __half2 h1 = __floats2half2_rn(v.z, v.w);
    uint2 r;
    r.x = *reinterpret_cast<uint32_t*>(&h0);
    r.y = *reinterpret_cast<uint32_t*>(&h1);
    return r;
}

__global__ __launch_bounds__(256) void conv_a(
    const float* __restrict__ x, const float* __restrict__ xt)
{
    size_t i = (size_t)blockIdx.x * 256 + threadIdx.x;   // 8-elem index
    if (i >= (size_t)M_PAD * (D / 8)) return;
    size_t row = i / (D / 8);
    int    c8  = (int)(i % (D / 8)) * 8;
    float4 v0 = make_float4(0.f, 0.f, 0.f, 0.f), v1 = v0;
    if (row < M_X) {
        const float* p = x + row * D + c8;
        v0 = *reinterpret_cast<const float4*>(p);
        v1 = *reinterpret_cast<const float4*>(p + 4);
    } else if (row < M_TOT) {
        const float* p = xt + (row - M_X) * D + c8;
        v0 = *reinterpret_cast<const float4*>(p);
        v1 = *reinterpret_cast<const float4*>(p + 4);
    }
    uint2 a = cvt4(v0), bb = cvt4(v1);
    uint4 o; o.x = a.x; o.y = a.y; o.z = bb.x; o.w = bb.y;
    *reinterpret_cast<uint4*>(&g_Ah[row * D + c8]) = o;
}

__global__ __launch_bounds__(256) void conv_b(const float* __restrict__ W)
{
    size_t i = (size_t)blockIdx.x * 256 + threadIdx.x;
    // fused: zero the scatter-atomic partial slot (runs before scatter on s2)
    if (i < D) g_partial[(size_t)GP_SCAT * D + i] = 0.f;
    if (i >= (size_t)D * (D / 8)) return;
    size_t row = i / (D / 8);
    int    c8  = (int)(i % (D / 8)) * 8;
    const float* p = W + row * D + c8;
    float4 v0 = *reinterpret_cast<const float4*>(p);
    float4 v1 = *reinterpret_cast<const float4*>(p + 4);
    uint2 a = cvt4(v0), bb = cvt4(v1);
    uint4 o; o.x = a.x; o.y = a.y; o.z = bb.x; o.w = bb.y;
    *reinterpret_cast<uint4*>(&g_Bh[row * D + c8]) = o;
}

// ---------------------------------------------------------------------------
// noise / scatter (abs partials fused — no 50 MB re-read kernel)
// ---------------------------------------------------------------------------
__global__ __launch_bounds__(256) void noise_gemv(
    const float* __restrict__ x, const float* __restrict__ W,
    float* __restrict__ out)
{
    int j = blockIdx.x;
    const float* xr = x + (size_t)8193 * D;
    const float* wr = W + (size_t)j * D;
    float s = 0.f;
    for (int k = threadIdx.x * 4; k < D; k += 256 * 4) {
        float4 xv = *reinterpret_cast<const float4*>(xr + k);
        float4 wv = *reinterpret_cast<const float4*>(wr + k);
        s += xv.x * fabsf(wv.x) + xv.y * fabsf(wv.y)
           + xv.z * fabsf(wv.z) + xv.w * fabsf(wv.w);
    }
    __shared__ float red[256];
    red[threadIdx.x] = s;
    __syncthreads();
    #pragma unroll
    for (int o = 128; o > 0; o >>= 1) {
        if (threadIdx.x < o) red[threadIdx.x] += red[threadIdx.x + o];
        __syncthreads();
    }
    if (threadIdx.x == 0) {
        out[(size_t)ROW_NOISE * D + j] = red[0];
        g_partial[(size_t)GP_NOISE * D + j] = fabsf(red[0]);
    }
}

__global__ void scatter_kernel(
    const float* __restrict__ x,
    const float* __restrict__ w_val, const int* __restrict__ w_idx,
    const float* __restrict__ b_val, const int* __restrict__ b_idx,
    float* __restrict__ out)
{
    int i = blockIdx.x * 256 + threadIdx.x;
    if (i < NW) {
        int idx = w_idx[i];
        int row = idx / D;
        int col = idx % D;
        float v = w_val[i] * x[col];
        out[(size_t)(ROW_ADDW + i) * D + row] = v;
        atomicAdd(&g_partial[(size_t)GP_SCAT * D + row], fabsf(v));
    }
    if (i < NB) {
        float v = b_val[i];
        out[(size_t)(ROW_ADDB + i) * D + b_idx[i]] = v;
        atomicAdd(&g_partial[(size_t)GP_SCAT * D + b_idx[i]], fabsf(v));
    }
}

__global__ __launch_bounds__(256) void finalize_minmax(float* __restrict__ out)
{
    int col = blockIdx.x * 256 + threadIdx.x;
    float s = 0.f;
    for (int c = 0; c < GP_TOTAL; c++)
        s += g_partial[(size_t)c * D + col];
    float v = out[col];
    out[XMIN_OFF + col] = v - s;
    out[XMAX_OFF + col] = v + s;
}

// ---------------------------------------------------------------------------
// Host side
// ---------------------------------------------------------------------------
typedef CUresult (*PFN_tmEncode)(
    CUtensorMap*, CUtensorMapDataType, cuuint32_t, void*,
    const cuuint64_t*, const cuuint64_t*, const cuuint32_t*, const cuuint32_t*,
    CUtensorMapInterleave, CUtensorMapSwizzle, CUtensorMapL2promotion,
    CUtensorMapFloatOOBfill);

static void make_map(PFN_tmEncode enc, CUtensorMap* m, void* ptr,
                     uint64_t rows, uint32_t box_rows)
{
    cuuint64_t dims[2]    = {(cuuint64_t)D, (cuuint64_t)rows};
    cuuint64_t strides[1] = {(cuuint64_t)D * sizeof(__half)};
    cuuint32_t box[2]     = {KC, box_rows};
    cuuint32_t estr[2]    = {1, 1};
    enc(m, CU_TENSOR_MAP_DATA_TYPE_FLOAT16, 2, ptr, dims, strides, box, estr,
        CU_TENSOR_MAP_INTERLEAVE_NONE, CU_TENSOR_MAP_SWIZZLE_128B,
        CU_TENSOR_MAP_L2_PROMOTION_L2_128B, CU_TENSOR_MAP_FLOAT_OOB_FILL_NONE);
}

extern "C" void kernel_launch(void* const* d_in, const int* in_sizes, int n_in,
                              void* d_out, int out_size)
{
    const float* x     = (const float*)d_in[0];
    const float* xtrue = (const float*)d_in[1];
    const float* W     = (const float*)d_in[2];
    const float* b     = (const float*)d_in[3];
    const float* w_val = (const float*)d_in[4];
    const float* b_val = (const float*)d_in[5];
    const int*   w_idx = (const int*)d_in[6];
    const int*   b_idx = (const int*)d_in[7];
    float* out = (float*)d_out;

    PFN_tmEncode enc = nullptr;
    {
        cudaDriverEntryPointQueryResult qr;
        void* fn = nullptr;
        cudaGetDriverEntryPointByVersion("cuTensorMapEncodeTiled", &fn, 12000,
                                         cudaEnableDefault, &qr);
        enc = (PFN_tmEncode)fn;
    }

    void *pA = nullptr, *pB = nullptr;
    cudaGetSymbolAddress(&pA, g_Ah);
    cudaGetSymbolAddress(&pB, g_Bh);

    CUtensorMap tA, tB;
    make_map(enc, &tA, pA, M_PAD, MT);
    make_map(enc, &tB, pB, D, NT);

    cudaFuncSetAttribute(gemm_hmma, cudaFuncAttributeMaxDynamicSharedMemorySize,
                         SM_TOTAL);

    // One-time side-stream + events (created once; every call enqueues the
    // identical DAG, so kernel_launch stays deterministic & capturable).
    static cudaStream_t s2 = nullptr;
    static cudaEvent_t evFork = nullptr, evJoin = nullptr, evConvB = nullptr;
    if (s2 == nullptr) {
        cudaStreamCreateWithFlags(&s2, cudaStreamNonBlocking);
        cudaEventCreateWithFlags(&evFork, cudaEventDisableTiming);
        cudaEventCreateWithFlags(&evJoin, cudaEventDisableTiming);
        cudaEventCreateWithFlags(&evConvB, cudaEventDisableTiming);
    }

    // ---- fork: side chain runs concurrent with conv_a / GEMM ----
    cudaEventRecord(evFork, (cudaStream_t)0);
    cudaStreamWaitEvent(s2, evFork, 0);

    // side stream: conv_b (+GP_SCAT zero, overlaps conv_a) -> memset ->
    //              scatter -> noise
    conv_b<<<(unsigned)(((size_t)D * (D / 8) + 255) / 256), 256, 0, s2>>>(W);
    cudaEventRecord(evConvB, s2);
    cudaMemsetAsync(out + (size_t)ROW_ADDW * D, 0,
                    (size_t)(NW + NB) * D * sizeof(float), s2);
    scatter_kernel<<<(NW + 255) / 256, 256, 0, s2>>>(x, w_val, w_idx, b_val,
                                                     b_idx, out);
    noise_gemv<<<D, 256, 0, s2>>>(x, W, out);
    cudaEventRecord(evJoin, s2);

    // main stream: conv_a -> (wait conv_b) -> GEMM
    conv_a<<<(unsigned)(((size_t)M_PAD * (D / 8) + 255) / 256), 256>>>(x, xtrue);
    cudaStreamWaitEvent((cudaStream_t)0, evConvB, 0);

    dim3 ggrid(D / NT, M_PAD / MT);          // (16, 65)
    gemm_hmma<<<ggrid, 256, SM_TOTAL>>>(tA, tB, b, out);

    // join + finalize
    cudaStreamWaitEvent((cudaStream_t)0, evJoin, 0);
    finalize_minmax<<<D / 256, 256>>>(out);
}

// round 14
// speedup vs baseline: 1.0150x; 1.0150x over previous
#include <cuda_runtime.h>
#include <cuda.h>
#include <cuda_fp16.h>
#include <cstdint>

// ---------------------------------------------------------------------------
// Geometry
// ---------------------------------------------------------------------------
#define D        2048
#define M_X      8193
#define M_TOT    8225              // x rows + 32 x_true rows
#define M_PAD    8320              // 65 * 128
#define ROW_ADDW 8193
#define ROW_ADDB 12289
#define ROW_NOISE 14337
#define XOUT_ROWS 14338
#define NW 4096
#define NB 2048

#define XMIN_OFF  ((size_t)XOUT_ROWS * D)
#define XMAX_OFF  (XMIN_OFF + D)
#define XTRUE_OFF (XMAX_OFF + D)

// partial slots: 65 gemm CTA-rows + 1 scatter-atomic slot + 1 noise slot = 67
#define GP_GEMM   0
#define GP_SCAT   65
#define GP_NOISE  66
#define GP_TOTAL  67
__device__ float g_partial[128 * D];

// fp16 buffers (scratch via __device__ globals — allowed)
__device__ __align__(1024) __half g_Ah[(size_t)M_PAD * D];
__device__ __align__(1024) __half g_Bh[(size_t)D * D];

// ---------------------------------------------------------------------------
// PTX helpers (baseline sm_90 features only — NO tcgen05 on this toolchain)
// ---------------------------------------------------------------------------
__device__ __forceinline__ uint32_t s2u(const void* p) {
    return (uint32_t)__cvta_generic_to_shared(p);
}

#define MBAR_INIT(a, n) \
    asm volatile("mbarrier.init.shared.b64 [%0], %1;" :: "r"(a), "r"((uint32_t)(n)) : "memory")
#define MBAR_EXPECT_TX(a, b) \
    asm volatile("mbarrier.arrive.expect_tx.shared.b64 _, [%0], %1;" :: "r"(a), "r"((uint32_t)(b)) : "memory")
#define MBAR_ARRIVE(a) \
    asm volatile("mbarrier.arrive.shared.b64 _, [%0];" :: "r"(a) : "memory")

__device__ __forceinline__ void mbar_wait(uint32_t mbar, uint32_t parity) {
    asm volatile(
        "{\n\t.reg .pred P;\n\t"
        "WL_%=:\n\t"
        "mbarrier.try_wait.parity.acquire.cta.shared::cta.b64 P, [%0], %1, 0x989680;\n\t"
        "@P bra.uni WD_%=;\n\t"
        "bra.uni WL_%=;\n\t"
        "WD_%=:\n\t}"
        :: "r"(mbar), "r"(parity) : "memory");
}

#define TMA_LD2D(saddr, map, cx, cy, mbar) \
    asm volatile("cp.async.bulk.tensor.2d.shared::cta.global.tile.mbarrier::complete_tx::bytes " \
                 "[%0], [%1, {%2, %3}], [%4];" \
                 :: "r"(saddr), "l"(map), "r"(cx), "r"(cy), "r"(mbar) : "memory")

#define LDSM_X4(d0, d1, d2, d3, a) \
    asm volatile("ldmatrix.sync.aligned.m8n8.x4.shared.b16 {%0,%1,%2,%3}, [%4];" \
                 : "=r"(d0), "=r"(d1), "=r"(d2), "=r"(d3) : "r"(a))

#define MMA_F16(c0, c1, c2, c3, a0, a1, a2, a3, b0, b1) \
    asm volatile("mma.sync.aligned.m16n8k16.row.col.f32.f16.f16.f32 " \
                 "{%0,%1,%2,%3}, {%4,%5,%6,%7}, {%8,%9}, {%0,%1,%2,%3};" \
                 : "+f"(c0), "+f"(c1), "+f"(c2), "+f"(c3) \
                 : "r"(a0), "r"(a1), "r"(a2), "r"(a3), "r"(b0), "r"(b1))

// ---------------------------------------------------------------------------
// GEMM config: 128x128 CTA tile, KC=64 per stage, 3-stage TMA pipeline,
// 2 CTAs/SM (96 KB smem, <=128 regs). 8 warps, 64x32 warp tiles.
// (Exact R12 measured-best configuration; per-warp-arrive variant regressed.)
// ---------------------------------------------------------------------------
#define MT 128
#define NT 128
#define KC 64
#define NSTAGE 3
#define NKIT (D / KC)               // 32
#define TILE_B   (128 * 128)        // 16384 B
#define STAGE_B  (2 * TILE_B)       // A, B = 32768 B
#define SM_TOTAL (NSTAGE * STAGE_B) // 98304 B

__global__ __launch_bounds__(256, 2) void gemm_hmma(
    const __grid_constant__ CUtensorMap tA,
    const __grid_constant__ CUtensorMap tB,
    const float* __restrict__ bias,
    float* __restrict__ out)
{
    extern __shared__ __align__(1024) char smem[];
    __shared__ __align__(8) uint64_t full_mb[NSTAGE];
    __shared__ __align__(8) uint64_t empty_mb[NSTAGE];

    const uint32_t sb  = s2u(smem);
    const int tid = threadIdx.x;
    const int wid = tid >> 5, lane = tid & 31;
    const int m0 = blockIdx.y * MT, n0 = blockIdx.x * NT;
    const int wy = wid & 1, wx = wid >> 1;          // warp tile 64(M) x 32(N)
    const int wm = wy * 64, wn = wx * 32;

    if (tid == 0) {
        #pragma unroll
        for (int s = 0; s < NSTAGE; ++s) {
            MBAR_INIT(s2u(&full_mb[s]), 1);
            MBAR_INIT(s2u(&empty_mb[s]), 256);
        }
    }
    asm volatile("fence.proxy.async.shared::cta;" ::: "memory");
    __syncthreads();

    // prologue: fill all stages
    if (tid == 0) {
        #pragma unroll
        for (int s = 0; s < NSTAGE; ++s) {
            uint32_t mb = s2u(&full_mb[s]);
            MBAR_EXPECT_TX(mb, STAGE_B);
            uint32_t sp = sb + s * STAGE_B;
            int k0 = s * KC;
            TMA_LD2D(sp,          &tA, k0, m0, mb);
            TMA_LD2D(sp + TILE_B, &tB, k0, n0, mb);
        }
    }

    // per-lane ldmatrix address pieces (SW128: chunk' = chunk ^ (row & 7))
    const int rA  = wm + ((lane >> 3) & 1) * 8 + (lane & 7);
    const int cgA = (lane >> 4) & 1;
    const int rB  = wn + ((lane >> 4) & 1) * 8 + (lane & 7);
    const int cgB = (lane >> 3) & 1;
    const int swA = rA & 7, swB = rB & 7;

    float acc[4][4][4];
    #pragma unroll
    for (int i = 0; i < 4; i++)
        #pragma unroll
        for (int j = 0; j < 4; j++)
            #pragma unroll
            for (int k = 0; k < 4; k++) acc[i][j][k] = 0.f;

    uint32_t A0[4][4], B0[4][2], A1[4][4], B1[4][2];

    #define LOAD_FRAGS(Af, Bf, sA, sB, ks)                                    \
        do {                                                                  \
            _Pragma("unroll")                                                 \
            for (int mi = 0; mi < 4; ++mi) {                                  \
                uint32_t a = (sA) + (rA + mi * 16) * 128                      \
                           + (((2 * (ks) + cgA) ^ swA) << 4);                 \
                LDSM_X4(Af[mi][0], Af[mi][1], Af[mi][2], Af[mi][3], a);       \
            }                                                                 \
            _Pragma("unroll")                                                 \
            for (int nb = 0; nb < 2; ++nb) {                                  \
                uint32_t a = (sB) + (rB + nb * 16) * 128                      \
                           + (((2 * (ks) + cgB) ^ swB) << 4);                 \
                LDSM_X4(Bf[nb * 2][0], Bf[nb * 2][1],                         \
                        Bf[nb * 2 + 1][0], Bf[nb * 2 + 1][1], a);             \
            }                                                                 \
        } while (0)

    #define MMA_ALL(Af, Bf)                                                   \
        do {                                                                  \
            _Pragma("unroll")                                                 \
            for (int mi = 0; mi < 4; ++mi)                                    \
                _Pragma("unroll")                                             \
                for (int nj = 0; nj < 4; ++nj)                                \
                    MMA_F16(acc[mi][nj][0], acc[mi][nj][1],                   \
                            acc[mi][nj][2], acc[mi][nj][3],                   \
                            Af[mi][0], Af[mi][1], Af[mi][2], Af[mi][3],       \
                            Bf[nj][0], Bf[nj][1]);                            \
        } while (0)

    for (int it = 0; it < NKIT; ++it) {
        const int slot = it % NSTAGE;
        const uint32_t ph = (uint32_t)((it / NSTAGE) & 1);
        mbar_wait(s2u(&full_mb[slot]), ph);

        const uint32_t sA = sb + slot * STAGE_B;
        const uint32_t sB = sA + TILE_B;

        LOAD_FRAGS(A0, B0, sA, sB, 0);
        LOAD_FRAGS(A1, B1, sA, sB, 1);
        MMA_ALL(A0, B0);
        LOAD_FRAGS(A0, B0, sA, sB, 2);
        MMA_ALL(A1, B1);
        LOAD_FRAGS(A1, B1, sA, sB, 3);
        // all LDSM reads of this slot are done
        MBAR_ARRIVE(s2u(&empty_mb[slot]));
        MMA_ALL(A0, B0);
        MMA_ALL(A1, B1);

        // producer refill (only tid 0): wait all 256 consumers released slot
        const int nx = it + NSTAGE;
        if (tid == 0 && nx < NKIT) {
            mbar_wait(s2u(&empty_mb[slot]), (uint32_t)((it / NSTAGE) & 1));
            uint32_t mb = s2u(&full_mb[slot]);
            MBAR_EXPECT_TX(mb, STAGE_B);
            uint32_t spn = sb + slot * STAGE_B;
            int k0 = nx * KC;
            TMA_LD2D(spn,          &tA, k0, m0, mb);
            TMA_LD2D(spn + TILE_B, &tB, k0, n0, mb);
        }
    }

    #undef LOAD_FRAGS
    #undef MMA_ALL

    // ---- epilogue: stores + fused |.| column partial over eps rows ----
    float colsum[4][2];
    #pragma unroll
    for (int nj = 0; nj < 4; ++nj) { colsum[nj][0] = 0.f; colsum[nj][1] = 0.f; }

    #pragma unroll
    for (int mi = 0; mi < 4; ++mi) {
        #pragma unroll
        for (int half = 0; half < 2; ++half) {
            int gm = m0 + wm + mi * 16 + (lane >> 2) + half * 8;
            if (gm >= M_TOT) continue;
            bool addb = (gm == 0) || (gm >= M_X);
            bool inabs = (gm >= 1) && (gm < M_X);     // eps rows only
            size_t base = (gm < M_X) ? (size_t)gm * D
                                     : XTRUE_OFF + (size_t)(gm - M_X) * D;
            #pragma unroll
            for (int nj = 0; nj < 4; ++nj) {
                int col = n0 + wn + nj * 8 + 2 * (lane & 3);
                float2 v;
                v.x = acc[mi][nj][half * 2 + 0];
                v.y = acc[mi][nj][half * 2 + 1];
                if (inabs) {
                    colsum[nj][0] += fabsf(v.x);
                    colsum[nj][1] += fabsf(v.y);
                }
                if (addb) { v.x += bias[col]; v.y += bias[col + 1]; }
                *reinterpret_cast<float2*>(&out[base + col]) = v;
            }
        }
    }

    // deterministic CTA-level column reduction: 16 contributors per column
    float* red = reinterpret_cast<float*>(smem);      // 128 cols x 16 = 8 KB
    const int cid = wy * 8 + (lane >> 2);
    __syncthreads();                                   // smem reuse safe
    #pragma unroll
    for (int nj = 0; nj < 4; ++nj) {
        int c0 = wn + nj * 8 + 2 * (lane & 3);
        red[(c0 + 0) * 16 + cid] = colsum[nj][0];
        red[(c0 + 1) * 16 + cid] = colsum[nj][1];
    }
    __syncthreads();
    if (tid < 128) {
        float s = 0.f;
        #pragma unroll
        for (int c = 0; c < 16; ++c) s += red[tid * 16 + c];
        g_partial[(size_t)(GP_GEMM + blockIdx.y) * D + n0 + tid] = s;
    }
}

// ---------------------------------------------------------------------------
// fp16 conversion — 8 elements per thread (2x float4 in, 1x uint4 out)
// ---------------------------------------------------------------------------
__device__ __forceinline__ uint2 cvt4(float4 v) {
    __half2 h0 = __floats2half2_rn(v.x, v.y);
    __half2 h1 = __floats2half2_rn(v.z, v.w);
    uint2 r;
    r.x = *reinterpret_cast<uint32_t*>(&h0);
    r.y = *reinterpret_cast<uint32_t*>(&h1);
    return r;
}

__global__ __launch_bounds__(256) void conv_a(
    const float* __restrict__ x, const float* __restrict__ xt)
{
    size_t i = (size_t)blockIdx.x * 256 + threadIdx.x;   // 8-elem index
    if (i >= (size_t)M_PAD * (D / 8)) return;
    size_t row = i / (D / 8);
    int    c8  = (int)(i % (D / 8)) * 8;
    float4 v0 = make_float4(0.f, 0.f, 0.f, 0.f), v1 = v0;
    if (row < M_X) {
        const float* p = x + row * D + c8;
        v0 = *reinterpret_cast<const float4*>(p);
        v1 = *reinterpret_cast<const float4*>(p + 4);
    } else if (row < M_TOT) {
        const float* p = xt + (row - M_X) * D + c8;
        v0 = *reinterpret_cast<const float4*>(p);
        v1 = *reinterpret_cast<const float4*>(p + 4);
    }
    uint2 a = cvt4(v0), bb = cvt4(v1);
    uint4 o; o.x = a.x; o.y = a.y; o.z = bb.x; o.w = bb.y;
    *reinterpret_cast<uint4*>(&g_Ah[row * D + c8]) = o;
}

__global__ __launch_bounds__(256) void conv_b(const float* __restrict__ W)
{
    size_t i = (size_t)blockIdx.x * 256 + threadIdx.x;
    // fused: zero the scatter-atomic partial slot (runs before scatter on s2)
    if (i < D) g_partial[(size_t)GP_SCAT * D + i] = 0.f;
    if (i >= (size_t)D * (D / 8)) return;
    size_t row = i / (D / 8);
    int    c8  = (int)(i % (D / 8)) * 8;
    const float* p = W + row * D + c8;
    float4 v0 = *reinterpret_cast<const float4*>(p);
    float4 v1 = *reinterpret_cast<const float4*>(p + 4);
    uint2 a = cvt4(v0), bb = cvt4(v1);
    uint4 o; o.x = a.x; o.y = a.y; o.z = bb.x; o.w = bb.y;
    *reinterpret_cast<uint4*>(&g_Bh[row * D + c8]) = o;
}

// ---------------------------------------------------------------------------
// noise / scatter (abs partials fused — no 50 MB re-read kernel)
// ---------------------------------------------------------------------------
__global__ __launch_bounds__(256) void noise_gemv(
    const float* __restrict__ x, const float* __restrict__ W,
    float* __restrict__ out)
{
    int j = blockIdx.x;
    const float* xr = x + (size_t)8193 * D;
    const float* wr = W + (size_t)j * D;
    float s = 0.f;
    for (int k = threadIdx.x * 4; k < D; k += 256 * 4) {
        float4 xv = *reinterpret_cast<const float4*>(xr + k);
        float4 wv = *reinterpret_cast<const float4*>(wr + k);
        s += xv.x * fabsf(wv.x) + xv.y * fabsf(wv.y)
           + xv.z * fabsf(wv.z) + xv.w * fabsf(wv.w);
    }
    __shared__ float red[256];
    red[threadIdx.x] = s;
    __syncthreads();
    #pragma unroll
    for (int o = 128; o > 0; o >>= 1) {
        if (threadIdx.x < o) red[threadIdx.x] += red[threadIdx.x + o];
        __syncthreads();
    }
    if (threadIdx.x == 0) {
        out[(size_t)ROW_NOISE * D + j] = red[0];
        g_partial[(size_t)GP_NOISE * D + j] = fabsf(red[0]);
    }
}

__global__ void scatter_kernel(
    const float* __restrict__ x,
    const float* __restrict__ w_val, const int* __restrict__ w_idx,
    const float* __restrict__ b_val, const int* __restrict__ b_idx,
    float* __restrict__ out)
{
    int i = blockIdx.x * 256 + threadIdx.x;
    if (i < NW) {
        int idx = w_idx[i];
        int row = idx / D;
        int col = idx % D;
        float v = w_val[i] * x[col];
        out[(size_t)(ROW_ADDW + i) * D + row] = v;
        atomicAdd(&g_partial[(size_t)GP_SCAT * D + row], fabsf(v));
    }
    if (i < NB) {
        float v = b_val[i];
        out[(size_t)(ROW_ADDB + i) * D + b_idx[i]] = v;
        atomicAdd(&g_partial[(size_t)GP_SCAT * D + b_idx[i]], fabsf(v));
    }
}

__global__ __launch_bounds__(256) void finalize_minmax(float* __restrict__ out)
{
    int col = blockIdx.x * 256 + threadIdx.x;
    float s = 0.f;
    for (int c = 0; c < GP_TOTAL; c++)
        s += g_partial[(size_t)c * D + col];
    float v = out[col];
    out[XMIN_OFF + col] = v - s;
    out[XMAX_OFF + col] = v + s;
}

// ---------------------------------------------------------------------------
// Host side
// ---------------------------------------------------------------------------
typedef CUresult (*PFN_tmEncode)(
    CUtensorMap*, CUtensorMapDataType, cuuint32_t, void*,
    const cuuint64_t*, const cuuint64_t*, const cuuint32_t*, const cuuint32_t*,
    CUtensorMapInterleave, CUtensorMapSwizzle, CUtensorMapL2promotion,
    CUtensorMapFloatOOBfill);

static void make_map(PFN_tmEncode enc, CUtensorMap* m, void* ptr,
                     uint64_t rows, uint32_t box_rows)
{
    cuuint64_t dims[2]    = {(cuuint64_t)D, (cuuint64_t)rows};
    cuuint64_t strides[1] = {(cuuint64_t)D * sizeof(__half)};
    cuuint32_t box[2]     = {KC, box_rows};
    cuuint32_t estr[2]    = {1, 1};
    enc(m, CU_TENSOR_MAP_DATA_TYPE_FLOAT16, 2, ptr, dims, strides, box, estr,
        CU_TENSOR_MAP_INTERLEAVE_NONE, CU_TENSOR_MAP_SWIZZLE_128B,
        CU_TENSOR_MAP_L2_PROMOTION_L2_128B, CU_TENSOR_MAP_FLOAT_OOB_FILL_NONE);
}

extern "C" void kernel_launch(void* const* d_in, const int* in_sizes, int n_in,
                              void* d_out, int out_size)
{
    const float* x     = (const float*)d_in[0];
    const float* xtrue = (const float*)d_in[1];
    const float* W     = (const float*)d_in[2];
    const float* b     = (const float*)d_in[3];
    const float* w_val = (const float*)d_in[4];
    const float* b_val = (const float*)d_in[5];
    const int*   w_idx = (const int*)d_in[6];
    const int*   b_idx = (const int*)d_in[7];
    float* out = (float*)d_out;

    PFN_tmEncode enc = nullptr;
    {
        cudaDriverEntryPointQueryResult qr;
        void* fn = nullptr;
        cudaGetDriverEntryPointByVersion("cuTensorMapEncodeTiled", &fn, 12000,
                                         cudaEnableDefault, &qr);
        enc = (PFN_tmEncode)fn;
    }

    void *pA = nullptr, *pB = nullptr;
    cudaGetSymbolAddress(&pA, g_Ah);
    cudaGetSymbolAddress(&pB, g_Bh);

    CUtensorMap tA, tB;
    make_map(enc, &tA, pA, M_PAD, MT);
    make_map(enc, &tB, pB, D, NT);

    cudaFuncSetAttribute(gemm_hmma, cudaFuncAttributeMaxDynamicSharedMemorySize,
                         SM_TOTAL);

    // One-time side-stream + events (created once; every call enqueues the
    // identical DAG, so kernel_launch stays deterministic & capturable).
    static cudaStream_t s2 = nullptr;
    static cudaEvent_t evFork = nullptr, evJoin = nullptr,
                       evConvB = nullptr, evConvA = nullptr;
    if (s2 == nullptr) {
        cudaStreamCreateWithFlags(&s2, cudaStreamNonBlocking);
        cudaEventCreateWithFlags(&evFork, cudaEventDisableTiming);
        cudaEventCreateWithFlags(&evJoin, cudaEventDisableTiming);
        cudaEventCreateWithFlags(&evConvB, cudaEventDisableTiming);
        cudaEventCreateWithFlags(&evConvA, cudaEventDisableTiming);
    }

    // ---- fork ----
    cudaEventRecord(evFork, (cudaStream_t)0);
    cudaStreamWaitEvent(s2, evFork, 0);

    // s2 phase 1: conv_b (+GP_SCAT zero) — GEMM dependency, shares DRAM with
    // conv_a only (no other traffic competing).
    conv_b<<<(unsigned)(((size_t)D * (D / 8) + 255) / 256), 256, 0, s2>>>(W);
    cudaEventRecord(evConvB, s2);

    // main: conv_a, then GEMM (after conv_b done)
    conv_a<<<(unsigned)(((size_t)M_PAD * (D / 8) + 255) / 256), 256>>>(x, xtrue);
    cudaEventRecord(evConvA, (cudaStream_t)0);
    cudaStreamWaitEvent((cudaStream_t)0, evConvB, 0);

    dim3 ggrid(D / NT, M_PAD / MT);          // (16, 65)
    gemm_hmma<<<ggrid, 256, SM_TOTAL>>>(tA, tB, b, out);

    // s2 phase 2: deferred until convs are done — memset/scatter/noise run
    // UNDER the GEMM (its DRAM util is ~6%), not against the conv phase.
    cudaStreamWaitEvent(s2, evConvA, 0);
    cudaMemsetAsync(out + (size_t)ROW_ADDW * D, 0,
                    (size_t)(NW + NB) * D * sizeof(float), s2);
    scatter_kernel<<<(NW + 255) / 256, 256, 0, s2>>>(x, w_val, w_idx, b_val,
                                                     b_idx, out);
    noise_gemv<<<D, 256, 0, s2>>>(x, W, out);
    cudaEventRecord(evJoin, s2);

    // join + finalize
    cudaStreamWaitEvent((cudaStream_t)0, evJoin, 0);
    finalize_minmax<<<D / 256, 256>>>(out);
}

// round 16
// speedup vs baseline: 1.0215x; 1.0065x over previous
#include <cuda_runtime.h>
#include <cuda.h>
#include <cuda_fp16.h>
#include <cstdint>

// ---------------------------------------------------------------------------
// Geometry
// ---------------------------------------------------------------------------
#define D        2048
#define M_X      8193
#define M_TOT    8225              // x rows + 32 x_true rows
#define M_PAD    8320              // 65 * 128
#define ROW_ADDW 8193
#define ROW_ADDB 12289
#define ROW_NOISE 14337
#define XOUT_ROWS 14338
#define NW 4096
#define NB 2048

#define XMIN_OFF  ((size_t)XOUT_ROWS * D)
#define XMAX_OFF  (XMIN_OFF + D)
#define XTRUE_OFF (XMAX_OFF + D)

// partial slots: 65 gemm CTA-rows + 1 scatter-atomic slot + 1 noise slot = 67
#define GP_GEMM   0
#define GP_SCAT   65
#define GP_NOISE  66
#define GP_TOTAL  67
__device__ float g_partial[128 * D];

// fp16 buffers (scratch via __device__ globals — allowed)
__device__ __align__(1024) __half g_Ah[(size_t)M_PAD * D];
__device__ __align__(1024) __half g_Bh[(size_t)D * D];

// ---------------------------------------------------------------------------
// PTX helpers (baseline sm_90 features only — NO tcgen05 on this toolchain)
// ---------------------------------------------------------------------------
__device__ __forceinline__ uint32_t s2u(const void* p) {
    return (uint32_t)__cvta_generic_to_shared(p);
}

#define MBAR_INIT(a, n) \
    asm volatile("mbarrier.init.shared.b64 [%0], %1;" :: "r"(a), "r"((uint32_t)(n)) : "memory")
#define MBAR_EXPECT_TX(a, b) \
    asm volatile("mbarrier.arrive.expect_tx.shared.b64 _, [%0], %1;" :: "r"(a), "r"((uint32_t)(b)) : "memory")
#define MBAR_ARRIVE(a) \
    asm volatile("mbarrier.arrive.shared.b64 _, [%0];" :: "r"(a) : "memory")

__device__ __forceinline__ void mbar_wait(uint32_t mbar, uint32_t parity) {
    asm volatile(
        "{\n\t.reg .pred P;\n\t"
        "WL_%=:\n\t"
        "mbarrier.try_wait.parity.acquire.cta.shared::cta.b64 P, [%0], %1, 0x989680;\n\t"
        "@P bra.uni WD_%=;\n\t"
        "bra.uni WL_%=;\n\t"
        "WD_%=:\n\t}"
        :: "r"(mbar), "r"(parity) : "memory");
}

#define TMA_LD2D(saddr, map, cx, cy, mbar) \
    asm volatile("cp.async.bulk.tensor.2d.shared::cta.global.tile.mbarrier::complete_tx::bytes " \
                 "[%0], [%1, {%2, %3}], [%4];" \
                 :: "r"(saddr), "l"(map), "r"(cx), "r"(cy), "r"(mbar) : "memory")

#define LDSM_X4(d0, d1, d2, d3, a) \
    asm volatile("ldmatrix.sync.aligned.m8n8.x4.shared.b16 {%0,%1,%2,%3}, [%4];" \
                 : "=r"(d0), "=r"(d1), "=r"(d2), "=r"(d3) : "r"(a))

#define MMA_F16(c0, c1, c2, c3, a0, a1, a2, a3, b0, b1) \
    asm volatile("mma.sync.aligned.m16n8k16.row.col.f32.f16.f16.f32 " \
                 "{%0,%1,%2,%3}, {%4,%5,%6,%7}, {%8,%9}, {%0,%1,%2,%3};" \
                 : "+f"(c0), "+f"(c1), "+f"(c2), "+f"(c3) \
                 : "r"(a0), "r"(a1), "r"(a2), "r"(a3), "r"(b0), "r"(b1))

// ---------------------------------------------------------------------------
// GEMM config: 128x128 CTA tile, KC=64 per stage, 3-stage TMA pipeline,
// 2 CTAs/SM (96 KB smem, <=128 regs). 8 warps, 64x32 warp tiles.
// (Exact R12 measured-best configuration. Refill stays AFTER the trailing
// MMAs — the consuming MMAs force LDSM completion before the slot is
// released for TMA overwrite; the hoisted variant raced and failed.)
// ---------------------------------------------------------------------------
#define MT 128
#define NT 128
#define KC 64
#define NSTAGE 3
#define NKIT (D / KC)               // 32
#define TILE_B   (128 * 128)        // 16384 B
#define STAGE_B  (2 * TILE_B)       // A, B = 32768 B
#define SM_TOTAL (NSTAGE * STAGE_B) // 98304 B

__global__ __launch_bounds__(256, 2) void gemm_hmma(
    const __grid_constant__ CUtensorMap tA,
    const __grid_constant__ CUtensorMap tB,
    const float* __restrict__ bias,
    float* __restrict__ out)
{
    extern __shared__ __align__(1024) char smem[];
    __shared__ __align__(8) uint64_t full_mb[NSTAGE];
    __shared__ __align__(8) uint64_t empty_mb[NSTAGE];

    const uint32_t sb  = s2u(smem);
    const int tid = threadIdx.x;
    const int wid = tid >> 5, lane = tid & 31;
    const int m0 = blockIdx.y * MT, n0 = blockIdx.x * NT;
    const int wy = wid & 1, wx = wid >> 1;          // warp tile 64(M) x 32(N)
    const int wm = wy * 64, wn = wx * 32;

    if (tid == 0) {
        #pragma unroll
        for (int s = 0; s < NSTAGE; ++s) {
            MBAR_INIT(s2u(&full_mb[s]), 1);
            MBAR_INIT(s2u(&empty_mb[s]), 256);
        }
    }
    asm volatile("fence.proxy.async.shared::cta;" ::: "memory");
    __syncthreads();

    // prologue: fill all stages
    if (tid == 0) {
        #pragma unroll
        for (int s = 0; s < NSTAGE; ++s) {
            uint32_t mb = s2u(&full_mb[s]);
            MBAR_EXPECT_TX(mb, STAGE_B);
            uint32_t sp = sb + s * STAGE_B;
            int k0 = s * KC;
            TMA_LD2D(sp,          &tA, k0, m0, mb);
            TMA_LD2D(sp + TILE_B, &tB, k0, n0, mb);
        }
    }

    // per-lane ldmatrix address pieces (SW128: chunk' = chunk ^ (row & 7))
    const int rA  = wm + ((lane >> 3) & 1) * 8 + (lane & 7);
    const int cgA = (lane >> 4) & 1;
    const int rB  = wn + ((lane >> 4) & 1) * 8 + (lane & 7);
    const int cgB = (lane >> 3) & 1;
    const int swA = rA & 7, swB = rB & 7;

    float acc[4][4][4];
    #pragma unroll
    for (int i = 0; i < 4; i++)
        #pragma unroll
        for (int j = 0; j < 4; j++)
            #pragma unroll
            for (int k = 0; k < 4; k++) acc[i][j][k] = 0.f;

    uint32_t A0[4][4], B0[4][2], A1[4][4], B1[4][2];

    #define LOAD_FRAGS(Af, Bf, sA, sB, ks)                                    \
        do {                                                                  \
            _Pragma("unroll")                                                 \
            for (int mi = 0; mi < 4; ++mi) {                                  \
                uint32_t a = (sA) + (rA + mi * 16) * 128                      \
                           + (((2 * (ks) + cgA) ^ swA) << 4);                 \
                LDSM_X4(Af[mi][0], Af[mi][1], Af[mi][2], Af[mi][3], a);       \
            }                                                                 \
            _Pragma("unroll")                                                 \
            for (int nb = 0; nb < 2; ++nb) {                                  \
                uint32_t a = (sB) + (rB + nb * 16) * 128                      \
                           + (((2 * (ks) + cgB) ^ swB) << 4);                 \
                LDSM_X4(Bf[nb * 2][0], Bf[nb * 2][1],                         \
                        Bf[nb * 2 + 1][0], Bf[nb * 2 + 1][1], a);             \
            }                                                                 \
        } while (0)

    #define MMA_ALL(Af, Bf)                                                   \
        do {                                                                  \
            _Pragma("unroll")                                                 \
            for (int mi = 0; mi < 4; ++mi)                                    \
                _Pragma("unroll")                                             \
                for (int nj = 0; nj < 4; ++nj)                                \
                    MMA_F16(acc[mi][nj][0], acc[mi][nj][1],                   \
                            acc[mi][nj][2], acc[mi][nj][3],                   \
                            Af[mi][0], Af[mi][1], Af[mi][2], Af[mi][3],       \
                            Bf[nj][0], Bf[nj][1]);                            \
        } while (0)

    for (int it = 0; it < NKIT; ++it) {
        const int slot = it % NSTAGE;
        const uint32_t ph = (uint32_t)((it / NSTAGE) & 1);
        mbar_wait(s2u(&full_mb[slot]), ph);

        const uint32_t sA = sb + slot * STAGE_B;
        const uint32_t sB = sA + TILE_B;

        LOAD_FRAGS(A0, B0, sA, sB, 0);
        LOAD_FRAGS(A1, B1, sA, sB, 1);
        MMA_ALL(A0, B0);
        LOAD_FRAGS(A0, B0, sA, sB, 2);
        MMA_ALL(A1, B1);
        LOAD_FRAGS(A1, B1, sA, sB, 3);
        // all LDSM reads of this slot are done
        MBAR_ARRIVE(s2u(&empty_mb[slot]));
        MMA_ALL(A0, B0);
        MMA_ALL(A1, B1);

        // producer refill (only tid 0): wait all 256 consumers released slot
        const int nx = it + NSTAGE;
        if (tid == 0 && nx < NKIT) {
            mbar_wait(s2u(&empty_mb[slot]), (uint32_t)((it / NSTAGE) & 1));
            uint32_t mb = s2u(&full_mb[slot]);
            MBAR_EXPECT_TX(mb, STAGE_B);
            uint32_t spn = sb + slot * STAGE_B;
            int k0 = nx * KC;
            TMA_LD2D(spn,          &tA, k0, m0, mb);
            TMA_LD2D(spn + TILE_B, &tB, k0, n0, mb);
        }
    }

    #undef LOAD_FRAGS
    #undef MMA_ALL

    // ---- epilogue: stores + fused |.| column partial over eps rows ----
    float colsum[4][2];
    #pragma unroll
    for (int nj = 0; nj < 4; ++nj) { colsum[nj][0] = 0.f; colsum[nj][1] = 0.f; }

    #pragma unroll
    for (int mi = 0; mi < 4; ++mi) {
        #pragma unroll
        for (int half = 0; half < 2; ++half) {
            int gm = m0 + wm + mi * 16 + (lane >> 2) + half * 8;
            if (gm >= M_TOT) continue;
            bool addb = (gm == 0) || (gm >= M_X);
            bool inabs = (gm >= 1) && (gm < M_X);     // eps rows only
            size_t base = (gm < M_X) ? (size_t)gm * D
                                     : XTRUE_OFF + (size_t)(gm - M_X) * D;
            #pragma unroll
            for (int nj = 0; nj < 4; ++nj) {
                int col = n0 + wn + nj * 8 + 2 * (lane & 3);
                float2 v;
                v.x = acc[mi][nj][half * 2 + 0];
                v.y = acc[mi][nj][half * 2 + 1];
                if (inabs) {
                    colsum[nj][0] += fabsf(v.x);
                    colsum[nj][1] += fabsf(v.y);
                }
                if (addb) { v.x += bias[col]; v.y += bias[col + 1]; }
                *reinterpret_cast<float2*>(&out[base + col]) = v;
            }
        }
    }

    // deterministic CTA-level column reduction: 16 contributors per column
    float* red = reinterpret_cast<float*>(smem);      // 128 cols x 16 = 8 KB
    const int cid = wy * 8 + (lane >> 2);
    __syncthreads();                                   // smem reuse safe
    #pragma unroll
    for (int nj = 0; nj < 4; ++nj) {
        int c0 = wn + nj * 8 + 2 * (lane & 3);
        red[(c0 + 0) * 16 + cid] = colsum[nj][0];
        red[(c0 + 1) * 16 + cid] = colsum[nj][1];
    }
    __syncthreads();
    if (tid < 128) {
        float s = 0.f;
        #pragma unroll
        for (int c = 0; c < 16; ++c) s += red[tid * 16 + c];
        g_partial[(size_t)(GP_GEMM + blockIdx.y) * D + n0 + tid] = s;
    }
}

// ---------------------------------------------------------------------------
// fp16 conversion — 8 elements per thread (2x float4 in, 1x uint4 out)
// ---------------------------------------------------------------------------
__device__ __forceinline__ uint2 cvt4(float4 v) {
    __half2 h0 = __floats2half2_rn(v.x, v.y);
    __half2 h1 = __floats2half2_rn(v.z, v.w);
    uint2 r;
    r.x = *reinterpret_cast<uint32_t*>(&h0);
    r.y = *reinterpret_cast<uint32_t*>(&h1);
    return r;
}

__global__ __launch_bounds__(256) void conv_a(
    const float* __restrict__ x, const float* __restrict__ xt)
{
    size_t i = (size_t)blockIdx.x * 256 + threadIdx.x;   // 8-elem index
    if (i >= (size_t)M_PAD * (D / 8)) return;
    size_t row = i / (D / 8);
    int    c8  = (int)(i % (D / 8)) * 8;
    float4 v0 = make_float4(0.f, 0.f, 0.f, 0.f), v1 = v0;
    if (row < M_X) {
        const float* p = x + row * D + c8;
        v0 = *reinterpret_cast<const float4*>(p);
        v1 = *reinterpret_cast<const float4*>(p + 4);
    } else if (row < M_TOT) {
        const float* p = xt + (row - M_X) * D + c8;
        v0 = *reinterpret_cast<const float4*>(p);
        v1 = *reinterpret_cast<const float4*>(p + 4);
    }
    uint2 a = cvt4(v0), bb = cvt4(v1);
    uint4 o; o.x = a.x; o.y = a.y; o.z = bb.x; o.w = bb.y;
    *reinterpret_cast<uint4*>(&g_Ah[row * D + c8]) = o;
}

__global__ __launch_bounds__(256) void conv_b(const float* __restrict__ W)
{
    size_t i = (size_t)blockIdx.x * 256 + threadIdx.x;
    // fused: zero the scatter-atomic partial slot (runs before scatter on s2)
    if (i < D) g_partial[(size_t)GP_SCAT * D + i] = 0.f;
    if (i >= (size_t)D * (D / 8)) return;
    size_t row = i / (D / 8);
    int    c8  = (int)(i % (D / 8)) * 8;
    const float* p = W + row * D + c8;
    float4 v0 = *reinterpret_cast<const float4*>(p);
    float4 v1 = *reinterpret_cast<const float4*>(p + 4);
    uint2 a = cvt4(v0), bb = cvt4(v1);
    uint4 o; o.x = a.x; o.y = a.y; o.z = bb.x; o.w = bb.y;
    *reinterpret_cast<uint4*>(&g_Bh[row * D + c8]) = o;
}

// ---------------------------------------------------------------------------
// noise / scatter (abs partials fused — no 50 MB re-read kernel)
// ---------------------------------------------------------------------------
__global__ __launch_bounds__(256) void noise_gemv(
    const float* __restrict__ x, const float* __restrict__ W,
    float* __restrict__ out)
{
    int j = blockIdx.x;
    const float* xr = x + (size_t)8193 * D;
    const float* wr = W + (size_t)j * D;
    float s = 0.f;
    for (int k = threadIdx.x * 4; k < D; k += 256 * 4) {
        float4 xv = *reinterpret_cast<const float4*>(xr + k);
        float4 wv = *reinterpret_cast<const float4*>(wr + k);
        s += xv.x * fabsf(wv.x) + xv.y * fabsf(wv.y)
           + xv.z * fabsf(wv.z) + xv.w * fabsf(wv.w);
    }
    __shared__ float red[256];
    red[threadIdx.x] = s;
    __syncthreads();
    #pragma unroll
    for (int o = 128; o > 0; o >>= 1) {
        if (threadIdx.x < o) red[threadIdx.x] += red[threadIdx.x + o];
        __syncthreads();
    }
    if (threadIdx.x == 0) {
        out[(size_t)ROW_NOISE * D + j] = red[0];
        g_partial[(size_t)GP_NOISE * D + j] = fabsf(red[0]);
    }
}

__global__ void scatter_kernel(
    const float* __restrict__ x,
    const float* __restrict__ w_val, const int* __restrict__ w_idx,
    const float* __restrict__ b_val, const int* __restrict__ b_idx,
    float* __restrict__ out)
{
    int i = blockIdx.x * 256 + threadIdx.x;
    if (i < NW) {
        int idx = w_idx[i];
        int row = idx / D;
        int col = idx % D;
        float v = w_val[i] * x[col];
        out[(size_t)(ROW_ADDW + i) * D + row] = v;
        atomicAdd(&g_partial[(size_t)GP_SCAT * D + row], fabsf(v));
    }
    if (i < NB) {
        float v = b_val[i];
        out[(size_t)(ROW_ADDB + i) * D + b_idx[i]] = v;
        atomicAdd(&g_partial[(size_t)GP_SCAT * D + b_idx[i]], fabsf(v));
    }
}

__global__ __launch_bounds__(256) void finalize_minmax(float* __restrict__ out)
{
    int col = blockIdx.x * 256 + threadIdx.x;
    float s = 0.f;
    for (int c = 0; c < GP_TOTAL; c++)
        s += g_partial[(size_t)c * D + col];
    float v = out[col];
    out[XMIN_OFF + col] = v - s;
    out[XMAX_OFF + col] = v + s;
}

// ---------------------------------------------------------------------------
// Host side
// ---------------------------------------------------------------------------
typedef CUresult (*PFN_tmEncode)(
    CUtensorMap*, CUtensorMapDataType, cuuint32_t, void*,
    const cuuint64_t*, const cuuint64_t*, const cuuint32_t*, const cuuint32_t*,
    CUtensorMapInterleave, CUtensorMapSwizzle, CUtensorMapL2promotion,
    CUtensorMapFloatOOBfill);

static void make_map(PFN_tmEncode enc, CUtensorMap* m, void* ptr,
                     uint64_t rows, uint32_t box_rows)
{
    cuuint64_t dims[2]    = {(cuuint64_t)D, (cuuint64_t)rows};
    cuuint64_t strides[1] = {(cuuint64_t)D * sizeof(__half)};
    cuuint32_t box[2]     = {KC, box_rows};
    cuuint32_t estr[2]    = {1, 1};
    enc(m, CU_TENSOR_MAP_DATA_TYPE_FLOAT16, 2, ptr, dims, strides, box, estr,
        CU_TENSOR_MAP_INTERLEAVE_NONE, CU_TENSOR_MAP_SWIZZLE_128B,
        CU_TENSOR_MAP_L2_PROMOTION_L2_128B, CU_TENSOR_MAP_FLOAT_OOB_FILL_NONE);
}

extern "C" void kernel_launch(void* const* d_in, const int* in_sizes, int n_in,
                              void* d_out, int out_size)
{
    const float* x     = (const float*)d_in[0];
    const float* xtrue = (const float*)d_in[1];
    const float* W     = (const float*)d_in[2];
    const float* b     = (const float*)d_in[3];
    const float* w_val = (const float*)d_in[4];
    const float* b_val = (const float*)d_in[5];
    const int*   w_idx = (const int*)d_in[6];
    const int*   b_idx = (const int*)d_in[7];
    float* out = (float*)d_out;

    PFN_tmEncode enc = nullptr;
    {
        cudaDriverEntryPointQueryResult qr;
        void* fn = nullptr;
        cudaGetDriverEntryPointByVersion("cuTensorMapEncodeTiled", &fn, 12000,
                                         cudaEnableDefault, &qr);
        enc = (PFN_tmEncode)fn;
    }

    void *pA = nullptr, *pB = nullptr;
    cudaGetSymbolAddress(&pA, g_Ah);
    cudaGetSymbolAddress(&pB, g_Bh);

    CUtensorMap tA, tB;
    make_map(enc, &tA, pA, M_PAD, MT);
    make_map(enc, &tB, pB, D, NT);

    cudaFuncSetAttribute(gemm_hmma, cudaFuncAttributeMaxDynamicSharedMemorySize,
                         SM_TOTAL);

    // One-time side-stream + events (created once; every call enqueues the
    // identical DAG, so kernel_launch stays deterministic & capturable).
    static cudaStream_t s2 = nullptr;
    static cudaEvent_t evFork = nullptr, evJoin = nullptr, evConvB = nullptr;
    if (s2 == nullptr) {
        cudaStreamCreateWithFlags(&s2, cudaStreamNonBlocking);
        cudaEventCreateWithFlags(&evFork, cudaEventDisableTiming);
        cudaEventCreateWithFlags(&evJoin, cudaEventDisableTiming);
        cudaEventCreateWithFlags(&evConvB, cudaEventDisableTiming);
    }

    // ---- fork: side chain runs concurrent with conv_a / GEMM ----
    cudaEventRecord(evFork, (cudaStream_t)0);
    cudaStreamWaitEvent(s2, evFork, 0);

    // side stream: conv_b (+GP_SCAT zero, overlaps conv_a) -> memset ->
    //              scatter -> noise  (R12 DAG — measured best)
    conv_b<<<(unsigned)(((size_t)D * (D / 8) + 255) / 256), 256, 0, s2>>>(W);
    cudaEventRecord(evConvB, s2);
    cudaMemsetAsync(out + (size_t)ROW_ADDW * D, 0,
                    (size_t)(NW + NB) * D * sizeof(float), s2);
    scatter_kernel<<<(NW + 255) / 256, 256, 0, s2>>>(x, w_val, w_idx, b_val,
                                                     b_idx, out);
    noise_gemv<<<D, 256, 0, s2>>>(x, W, out);
    cudaEventRecord(evJoin, s2);

    // main stream: conv_a -> (wait conv_b) -> GEMM
    conv_a<<<(unsigned)(((size_t)M_PAD * (D / 8) + 255) / 256), 256>>>(x, xtrue);
    cudaStreamWaitEvent((cudaStream_t)0, evConvB, 0);

    dim3 ggrid(D / NT, M_PAD / MT);          // (16, 65)
    gemm_hmma<<<ggrid, 256, SM_TOTAL>>>(tA, tB, b, out);

    // join + finalize
    cudaStreamWaitEvent((cudaStream_t)0, evJoin, 0);
    finalize_minmax<<<D / 256, 256>>>(out);
}